// round 5
// baseline (speedup 1.0000x reference)
#include <cuda_runtime.h>
#include <cstdint>

#define B_    64
#define S_    4096
#define F_    64
#define G4_   256   // 4 * F_

// ---------------- scratch (no cudaMalloc allowed) ----------------
__device__ float g_bufA[(size_t)B_ * S_ * F_];    // conv0 out / conv2 out
__device__ float g_h0[(size_t)B_ * S_ * F_];      // conv1 out, then h0 stream
__device__ float g_xw0[(size_t)B_ * S_ * G4_];    // layer0 gate pre-activations
__device__ int   g_prog[B_];                      // producer progress flags
__device__ float g_cfinal[B_ * F_];

typedef unsigned long long ull;

// ---------------- packed f32x2 helpers (sm_103a FFMA2 path) ----------------
__device__ __forceinline__ ull fma2(ull a, ull b, ull c) {
    ull d;
    asm("fma.rn.f32x2 %0, %1, %2, %3;" : "=l"(d) : "l"(a), "l"(b), "l"(c));
    return d;
}
__device__ __forceinline__ ull add2(ull a, ull b) {
    ull d;
    asm("add.rn.f32x2 %0, %1, %2;" : "=l"(d) : "l"(a), "l"(b));
    return d;
}
__device__ __forceinline__ ull pk2(float lo, float hi) {
    ull d;
    asm("mov.b64 %0, {%1, %2};" : "=l"(d) : "f"(lo), "f"(hi));
    return d;
}
__device__ __forceinline__ float2 upk2(ull v) {
    float2 r;
    asm("mov.b64 {%0, %1}, %2;" : "=f"(r.x), "=f"(r.y) : "l"(v));
    return r;
}

__device__ __forceinline__ float sigmoid_f(float x) {
    return __fdividef(1.0f, 1.0f + __expf(-x));
}
__device__ __forceinline__ float tanh_f(float x) {
    return __fdividef(2.0f, 1.0f + __expf(-2.0f * x)) - 1.0f;
}
// fast tanh for the c->h path only (HW tanh.approx, ~2^-11 accurate)
__device__ __forceinline__ float tanh_fast(float x) {
    float r;
    asm("tanh.approx.f32 %0, %1;" : "=f"(r) : "f"(x));
    return r;
}

// ---------------------------------------------------------------------------
// Fused conv1d / GEMM kernel. x slab stored as duplicated float2 so the
// broadcast operand of fma2 is a single LDS.64 (no dup mov).
// ---------------------------------------------------------------------------
template <int KW, bool RELU>
__global__ void __launch_bounds__(256)
conv_gemm(const float* __restrict__ xin, const float* __restrict__ w,
          const float* __restrict__ bias, float* __restrict__ out,
          int Cin, int Cout) {
    constexpr int PAD = KW / 2;
    constexpr int RX = 64 + KW - 1;

    __shared__ __align__(16) float2 xs2[66][16];
    __shared__ __align__(16) float ws[KW][16][64];

    const int tid = threadIdx.x;
    const int tx = tid & 15;
    const int ty = tid >> 4;
    const int s0 = blockIdx.x * 64;
    const int co0 = blockIdx.y * 64;
    const int b = blockIdx.z;

    const float* xb = xin + (size_t)b * S_ * Cin;

    ull a01[4], a23[4];
#pragma unroll
    for (int i = 0; i < 4; i++) { a01[i] = 0ull; a23[i] = 0ull; }

    for (int ck = 0; ck < Cin; ck += 16) {
        __syncthreads();
        for (int idx = tid; idx < RX * 16; idx += 256) {
            int r = idx >> 4, k = idx & 15;
            int sg = s0 + r - PAD;
            float v = 0.0f;
            if (sg >= 0 && sg < S_) v = xb[(size_t)sg * Cin + ck + k];
            xs2[r][k] = make_float2(v, v);
        }
        for (int idx = tid; idx < KW * 16 * 64; idx += 256) {
            int c = idx & 63, k = (idx >> 6) & 15, dk = idx >> 10;
            ws[dk][k][c] = w[((size_t)dk * Cin + (ck + k)) * Cout + co0 + c];
        }
        __syncthreads();

#pragma unroll
        for (int dk = 0; dk < KW; dk++) {
#pragma unroll
            for (int k = 0; k < 16; k++) {
                ulonglong2 wv =
                    *reinterpret_cast<const ulonglong2*>(&ws[dk][k][tx << 2]);
#pragma unroll
                for (int i = 0; i < 4; i++) {
                    ull av = *reinterpret_cast<const ull*>(
                        &xs2[ty * 4 + i + dk][k]);
                    a01[i] = fma2(av, wv.x, a01[i]);
                    a23[i] = fma2(av, wv.y, a23[i]);
                }
            }
        }
    }

    const int c0 = co0 + (tx << 2);
    const float bb0 = bias[c0 + 0], bb1 = bias[c0 + 1];
    const float bb2 = bias[c0 + 2], bb3 = bias[c0 + 3];
#pragma unroll
    for (int i = 0; i < 4; i++) {
        float2 v01 = upk2(a01[i]);
        float2 v23 = upk2(a23[i]);
        float4 o;
        o.x = v01.x + bb0; o.y = v01.y + bb1;
        o.z = v23.x + bb2; o.w = v23.y + bb3;
        if (RELU) {
            o.x = fmaxf(o.x, 0.0f); o.y = fmaxf(o.y, 0.0f);
            o.z = fmaxf(o.z, 0.0f); o.w = fmaxf(o.w, 0.0f);
        }
        int sg = s0 + ty * 4 + i;
        *reinterpret_cast<float4*>(&out[((size_t)b * S_ + sg) * Cout + c0]) = o;
    }
}

// ---------------------------------------------------------------------------
// Pipelined 2-layer LSTM recurrence.
// Blocks 0..63: layer0 producers — single Wh0 dot, publish h0[t] (64 floats)
// to global (lands in L2), flag every 4 steps.
// Blocks 64..127: layer1 consumers — compute BOTH Wx1.h0 and Wh1.h1 dots with
// register-resident weights; h0 staged via double-buffered SMEM ring fed by a
// register prefetch two 4-step blocks ahead (L2-hit latency fully covered).
// ---------------------------------------------------------------------------
__global__ void __launch_bounds__(256, 1)
lstm_pipe(const float* __restrict__ xw0, const float* __restrict__ Wh0,
          const float* __restrict__ Wx1, const float* __restrict__ b1v,
          const float* __restrict__ Wh1,
          float* __restrict__ h0g, int* __restrict__ prog,
          float* __restrict__ c_final) {
    const int b = blockIdx.x & 63;
    const bool producer = blockIdx.x < 64;
    const int g = threadIdx.x;
    const int gtype = g >> 6;

    __shared__ __align__(16) float h_s[F_];
    __shared__ float gbuf[G4_];
    __shared__ __align__(16) float h0s[2][4 * F_];   // consumer staging

    const ulonglong2* h4 = reinterpret_cast<const ulonglong2*>(h_s);

    if (producer) {
        ull wA[32];
#pragma unroll
        for (int k2 = 0; k2 < 32; k2++) {
            wA[k2] = pk2(Wh0[(size_t)(2 * k2) * G4_ + g],
                         Wh0[(size_t)(2 * k2 + 1) * G4_ + g]);
        }

        if (g < F_) h_s[g] = 0.0f;
        float c_reg = 0.0f;

        const float* xwb = xw0 + (size_t)b * S_ * G4_ + g;
        float* h0b = h0g + (size_t)b * S_ * F_;
        float xwbuf[4];
#pragma unroll
        for (int j = 0; j < 4; j++) xwbuf[j] = xwb[(size_t)j * G4_];
        __syncthreads();

        for (int t = 0; t < S_; t += 4) {
#pragma unroll
            for (int j = 0; j < 4; j++) {
                const int tj = t + j;
                float xv = xwbuf[j];
                int tn = tj + 4;
                if (tn < S_) xwbuf[j] = xwb[(size_t)tn * G4_];

                ull a0 = 0, a1 = 0, a2 = 0, a3 = 0;
#pragma unroll
                for (int k4 = 0; k4 < 16; k4 += 2) {
                    ulonglong2 hA = h4[k4];
                    ulonglong2 hB = h4[k4 + 1];
                    a0 = fma2(hA.x, wA[2 * k4 + 0], a0);
                    a1 = fma2(hA.y, wA[2 * k4 + 1], a1);
                    a2 = fma2(hB.x, wA[2 * k4 + 2], a2);
                    a3 = fma2(hB.y, wA[2 * k4 + 3], a3);
                }
                a0 = add2(add2(a0, a1), add2(a2, a3));
                float2 sa = upk2(a0);
                float pre = sa.x + sa.y + xv;

                float gv = (gtype == 2) ? tanh_f(pre) : sigmoid_f(pre);
                gbuf[g] = gv;
                __syncthreads();

                if (g < F_) {
                    float iv = gbuf[g];
                    float fv = gbuf[g + 64];
                    float gg = gbuf[g + 128];
                    float ov = gbuf[g + 192];
                    c_reg = fv * c_reg + iv * gg;
                    float hv = ov * tanh_fast(c_reg);
                    h_s[g] = hv;
                    __stcg(h0b + (size_t)tj * F_ + g, hv);   // publish h0
                }
                __syncthreads();
            }
            if (g == 0) {                 // release: h0[0..t+3] visible
                __threadfence();
                *(volatile int*)&prog[b] = t + 4;
            }
        }
    } else {
        // ---------------- consumer: layer1 recurrence (two dots) -----------
        ull wH[32], wX[32];
#pragma unroll
        for (int k2 = 0; k2 < 32; k2++) {
            wH[k2] = pk2(Wh1[(size_t)(2 * k2) * G4_ + g],
                         Wh1[(size_t)(2 * k2 + 1) * G4_ + g]);
            wX[k2] = pk2(Wx1[(size_t)(2 * k2) * G4_ + g],
                         Wx1[(size_t)(2 * k2 + 1) * G4_ + g]);
        }
        const float b1g = b1v[g];

        if (g < F_) h_s[g] = 0.0f;
        float c_reg = 0.0f;

        const float* h0b = h0g + (size_t)b * S_ * F_;
        const volatile int* pf = &prog[b];
        int seen = 0;

        // prime: blocks 0 and 1 of h0 (steps 0..3 and 4..7)
        while (seen < 8) { seen = *pf; if (seen < 8) __nanosleep(64); }
        __threadfence();
        float r0 = __ldcg(h0b + g);
        float rnext = __ldcg(h0b + 4 * F_ + g);
        h0s[0][g] = r0;
        __syncthreads();

        for (int t = 0; t < S_; t += 4) {
            const int k = t >> 2;
            float rfut = 0.0f;
            if (t + 8 < S_) {
                int need = t + 12; if (need > S_) need = S_;
                if (seen < need) {
                    while (seen < need) { seen = *pf; if (seen < need) __nanosleep(64); }
                    __threadfence();
                }
                rfut = __ldcg(h0b + (size_t)(t + 8) * F_ + g);
            }
            if (t + 4 < S_) h0s[(k + 1) & 1][g] = rnext;
            const float* h0blk = h0s[k & 1];

#pragma unroll
            for (int j = 0; j < 4; j++) {
                const ulonglong2* x4 =
                    reinterpret_cast<const ulonglong2*>(h0blk + j * F_);

                ull a0 = 0, a1 = 0, a2 = 0, a3 = 0;
                ull q0 = 0, q1 = 0, q2 = 0, q3 = 0;
#pragma unroll
                for (int k4 = 0; k4 < 16; k4 += 2) {
                    ulonglong2 hA = h4[k4];
                    ulonglong2 hB = h4[k4 + 1];
                    ulonglong2 xA = x4[k4];
                    ulonglong2 xB = x4[k4 + 1];
                    a0 = fma2(hA.x, wH[2 * k4 + 0], a0);
                    q0 = fma2(xA.x, wX[2 * k4 + 0], q0);
                    a1 = fma2(hA.y, wH[2 * k4 + 1], a1);
                    q1 = fma2(xA.y, wX[2 * k4 + 1], q1);
                    a2 = fma2(hB.x, wH[2 * k4 + 2], a2);
                    q2 = fma2(xB.x, wX[2 * k4 + 2], q2);
                    a3 = fma2(hB.y, wH[2 * k4 + 3], a3);
                    q3 = fma2(xB.y, wX[2 * k4 + 3], q3);
                }
                a0 = add2(add2(a0, a1), add2(a2, a3));
                q0 = add2(add2(q0, q1), add2(q2, q3));
                float2 sa = upk2(a0);
                float2 sq = upk2(q0);
                float pre = sa.x + sa.y + sq.x + sq.y + b1g;

                float gv = (gtype == 2) ? tanh_f(pre) : sigmoid_f(pre);
                gbuf[g] = gv;
                __syncthreads();

                if (g < F_) {
                    float iv = gbuf[g];
                    float fv = gbuf[g + 64];
                    float gg = gbuf[g + 128];
                    float ov = gbuf[g + 192];
                    c_reg = fv * c_reg + iv * gg;
                    h_s[g] = ov * tanh_fast(c_reg);
                }
                __syncthreads();
            }
            rnext = rfut;
        }
        if (g < F_) c_final[b * F_ + g] = c_reg;
    }
}

// ---------------------------------------------------------------------------
// Tiny dense head
// ---------------------------------------------------------------------------
__global__ void dense_head(const float* __restrict__ cf,
                           const float* __restrict__ wd,
                           const float* __restrict__ bd,
                           float* __restrict__ out) {
    int t = threadIdx.x;
    if (t >= B_ * 10) return;
    int b = t / 10, n = t % 10;
    float s = bd[n];
#pragma unroll
    for (int k = 0; k < F_; k++) s += cf[b * F_ + k] * wd[k * 10 + n];
    out[b * 10 + n] = s;
}

// ---------------------------------------------------------------------------
extern "C" void kernel_launch(void* const* d_in, const int* in_sizes, int n_in,
                              void* d_out, int out_size) {
    const float* x       = (const float*)d_in[0];
    const float* conv_w0 = (const float*)d_in[1];
    const float* conv_b0 = (const float*)d_in[2];
    const float* conv_w1 = (const float*)d_in[3];
    const float* conv_b1 = (const float*)d_in[4];
    const float* conv_w2 = (const float*)d_in[5];
    const float* conv_b2 = (const float*)d_in[6];
    const float* Wx0     = (const float*)d_in[7];
    const float* Wh0     = (const float*)d_in[8];
    const float* b0      = (const float*)d_in[9];
    const float* Wx1     = (const float*)d_in[10];
    const float* Wh1     = (const float*)d_in[11];
    const float* b1      = (const float*)d_in[12];
    const float* dense_w = (const float*)d_in[13];
    const float* dense_b = (const float*)d_in[14];
    float* out = (float*)d_out;

    void *pA, *pH0, *pXW0, *pPR, *pCF;
    cudaGetSymbolAddress(&pA, g_bufA);
    cudaGetSymbolAddress(&pH0, g_h0);
    cudaGetSymbolAddress(&pXW0, g_xw0);
    cudaGetSymbolAddress(&pPR, g_prog);
    cudaGetSymbolAddress(&pCF, g_cfinal);
    float* bufA = (float*)pA;
    float* h0b  = (float*)pH0;
    float* xw0  = (float*)pXW0;
    int*   prog = (int*)pPR;
    float* cfin = (float*)pCF;

    dim3 convGrid(S_ / 64, 1, B_);
    dim3 gemmGrid(S_ / 64, G4_ / 64, B_);

    // CNN stack (ping-pong bufA <-> h0b; h0b free until recurrence)
    conv_gemm<3, true><<<convGrid, 256>>>(x, conv_w0, conv_b0, bufA, 128, 64);
    conv_gemm<3, true><<<convGrid, 256>>>(bufA, conv_w1, conv_b1, h0b, 64, 64);
    conv_gemm<3, true><<<convGrid, 256>>>(h0b, conv_w2, conv_b2, bufA, 64, 64);

    // LSTM layer0 input projection (big parallel GEMM)
    conv_gemm<1, false><<<gemmGrid, 256>>>(bufA, Wx0, b0, xw0, 64, 256);

    // Pipelined 2-layer recurrence (h0 streamed through L2)
    lstm_pipe<<<2 * B_, 256>>>(xw0, Wh0, Wx1, b1, Wh1, h0b, prog, cfin);

    // Dense head
    dense_head<<<1, B_ * 10>>>(cfin, dense_w, dense_b, out);
}

// round 6
// speedup vs baseline: 1.7378x; 1.7378x over previous
#include <cuda_runtime.h>
#include <cstdint>

#define B_    64
#define S_    4096
#define F_    64
#define G4_   256   // 4 * F_

// ---------------- scratch (no cudaMalloc allowed) ----------------
__device__ float g_bufA[(size_t)B_ * S_ * F_];    // conv0 out / conv2 out
__device__ float g_bufB[(size_t)B_ * S_ * F_];    // conv1 out / h0 seq (unused now)
__device__ float g_xw0[(size_t)B_ * S_ * G4_];    // layer0 gate pre-activations
__device__ float g_xw1[(size_t)B_ * S_ * G4_];    // layer1 gate pre-activations
__device__ int   g_prog[B_];                      // producer progress flags
__device__ float g_cfinal[B_ * F_];

typedef unsigned long long ull;

// ---------------- packed f32x2 helpers (sm_103a FFMA2 path) ----------------
__device__ __forceinline__ ull fma2(ull a, ull b, ull c) {
    ull d;
    asm("fma.rn.f32x2 %0, %1, %2, %3;" : "=l"(d) : "l"(a), "l"(b), "l"(c));
    return d;
}
__device__ __forceinline__ ull add2(ull a, ull b) {
    ull d;
    asm("add.rn.f32x2 %0, %1, %2;" : "=l"(d) : "l"(a), "l"(b));
    return d;
}
__device__ __forceinline__ ull dup2(float a) {
    ull d;
    asm("mov.b64 %0, {%1, %1};" : "=l"(d) : "f"(a));
    return d;
}
__device__ __forceinline__ ull pk2(float lo, float hi) {
    ull d;
    asm("mov.b64 %0, {%1, %2};" : "=l"(d) : "f"(lo), "f"(hi));
    return d;
}
__device__ __forceinline__ float2 upk2(ull v) {
    float2 r;
    asm("mov.b64 {%0, %1}, %2;" : "=f"(r.x), "=f"(r.y) : "l"(v));
    return r;
}

// HW tanh.approx (single MUFU, ~1e-5 abs err) — used throughout the recurrence
__device__ __forceinline__ float tanh_fast(float x) {
    float r;
    asm("tanh.approx.f32 %0, %1;" : "=f"(r) : "f"(x));
    return r;
}
__device__ __forceinline__ float sig_fast(float x) {
    return fmaf(0.5f, tanh_fast(0.5f * x), 0.5f);
}

// ---------------------------------------------------------------------------
// Fused conv1d / GEMM kernel (exact R2 version — the float2-dup variant was a
// measured regression, reverted).
// ---------------------------------------------------------------------------
template <int KW, bool RELU>
__global__ void __launch_bounds__(256)
conv_gemm(const float* __restrict__ xin, const float* __restrict__ w,
          const float* __restrict__ bias, float* __restrict__ out,
          int Cin, int Cout) {
    constexpr int PAD = KW / 2;
    constexpr int RX = 64 + KW - 1;

    __shared__ __align__(16) float xs[66][16];
    __shared__ __align__(16) float ws[KW][16][64];

    const int tid = threadIdx.x;
    const int tx = tid & 15;
    const int ty = tid >> 4;
    const int s0 = blockIdx.x * 64;
    const int co0 = blockIdx.y * 64;
    const int b = blockIdx.z;

    const float* xb = xin + (size_t)b * S_ * Cin;

    ull a01[4], a23[4];
#pragma unroll
    for (int i = 0; i < 4; i++) { a01[i] = 0ull; a23[i] = 0ull; }

    for (int ck = 0; ck < Cin; ck += 16) {
        __syncthreads();
        for (int idx = tid; idx < RX * 16; idx += 256) {
            int r = idx >> 4, k = idx & 15;
            int sg = s0 + r - PAD;
            float v = 0.0f;
            if (sg >= 0 && sg < S_) v = xb[(size_t)sg * Cin + ck + k];
            xs[r][k] = v;
        }
        for (int idx = tid; idx < KW * 16 * 64; idx += 256) {
            int c = idx & 63, k = (idx >> 6) & 15, dk = idx >> 10;
            ws[dk][k][c] = w[((size_t)dk * Cin + (ck + k)) * Cout + co0 + c];
        }
        __syncthreads();

#pragma unroll
        for (int dk = 0; dk < KW; dk++) {
#pragma unroll
            for (int k = 0; k < 16; k++) {
                ulonglong2 wv =
                    *reinterpret_cast<const ulonglong2*>(&ws[dk][k][tx << 2]);
#pragma unroll
                for (int i = 0; i < 4; i++) {
                    ull av = dup2(xs[ty * 4 + i + dk][k]);
                    a01[i] = fma2(av, wv.x, a01[i]);
                    a23[i] = fma2(av, wv.y, a23[i]);
                }
            }
        }
    }

    const int c0 = co0 + (tx << 2);
    const float bb0 = bias[c0 + 0], bb1 = bias[c0 + 1];
    const float bb2 = bias[c0 + 2], bb3 = bias[c0 + 3];
#pragma unroll
    for (int i = 0; i < 4; i++) {
        float2 v01 = upk2(a01[i]);
        float2 v23 = upk2(a23[i]);
        float4 o;
        o.x = v01.x + bb0; o.y = v01.y + bb1;
        o.z = v23.x + bb2; o.w = v23.y + bb3;
        if (RELU) {
            o.x = fmaxf(o.x, 0.0f); o.y = fmaxf(o.y, 0.0f);
            o.z = fmaxf(o.z, 0.0f); o.w = fmaxf(o.w, 0.0f);
        }
        int sg = s0 + ty * 4 + i;
        *reinterpret_cast<float4*>(&out[((size_t)b * S_ + sg) * Cout + c0]) = o;
    }
}

// ---------------------------------------------------------------------------
// Pipelined 2-layer LSTM recurrence (exact R2 structure; only activations
// changed to single-MUFU tanh.approx forms).
// Blocks 0..63: layer0 producers — fused Wh0/Wx1 dots over shared h loads,
// publish xw1[t] and flag. Blocks 64..127: layer1 consumers.
// ---------------------------------------------------------------------------
__global__ void __launch_bounds__(256, 1)
lstm_pipe(const float* __restrict__ xw0, const float* __restrict__ Wh0,
          const float* __restrict__ Wx1, const float* __restrict__ b1v,
          const float* __restrict__ Wh1,
          float* __restrict__ xw1, int* __restrict__ prog,
          float* __restrict__ c_final) {
    const int b = blockIdx.x & 63;
    const bool producer = blockIdx.x < 64;
    const int g = threadIdx.x;
    const int gtype = g >> 6;

    __shared__ __align__(16) float h_s[F_];
    __shared__ float gbuf[G4_];

    const ulonglong2* h4 = reinterpret_cast<const ulonglong2*>(h_s);

    if (producer) {
        ull wA[32], wB[32];
#pragma unroll
        for (int k2 = 0; k2 < 32; k2++) {
            wA[k2] = pk2(Wh0[(size_t)(2 * k2) * G4_ + g],
                         Wh0[(size_t)(2 * k2 + 1) * G4_ + g]);
            wB[k2] = pk2(Wx1[(size_t)(2 * k2) * G4_ + g],
                         Wx1[(size_t)(2 * k2 + 1) * G4_ + g]);
        }
        const float b1g = b1v[g];

        if (g < F_) h_s[g] = 0.0f;
        float c_reg = 0.0f;

        const float* xwb = xw0 + (size_t)b * S_ * G4_ + g;
        float* xwo = xw1 + (size_t)b * S_ * G4_ + g;
        float xwbuf[4];
#pragma unroll
        for (int j = 0; j < 4; j++) xwbuf[j] = xwb[(size_t)j * G4_];
        __syncthreads();

        for (int t = 0; t < S_; t += 4) {
#pragma unroll
            for (int j = 0; j < 4; j++) {
                const int tj = t + j;
                float xv = xwbuf[j];
                int tn = tj + 4;
                if (tn < S_) xwbuf[j] = xwb[(size_t)tn * G4_];

                ull a0 = 0, a1 = 0, a2 = 0, a3 = 0;
                ull q0 = 0, q1 = 0, q2 = 0, q3 = 0;
#pragma unroll
                for (int k4 = 0; k4 < 16; k4 += 2) {
                    ulonglong2 hA = h4[k4];
                    ulonglong2 hB = h4[k4 + 1];
                    a0 = fma2(hA.x, wA[2 * k4 + 0], a0);
                    q0 = fma2(hA.x, wB[2 * k4 + 0], q0);
                    a1 = fma2(hA.y, wA[2 * k4 + 1], a1);
                    q1 = fma2(hA.y, wB[2 * k4 + 1], q1);
                    a2 = fma2(hB.x, wA[2 * k4 + 2], a2);
                    q2 = fma2(hB.x, wB[2 * k4 + 2], q2);
                    a3 = fma2(hB.y, wA[2 * k4 + 3], a3);
                    q3 = fma2(hB.y, wB[2 * k4 + 3], q3);
                }
                a0 = add2(add2(a0, a1), add2(a2, a3));
                q0 = add2(add2(q0, q1), add2(q2, q3));
                float2 sa = upk2(a0);
                float2 sq = upk2(q0);
                float pre = sa.x + sa.y + xv;

                float gv = (gtype == 2) ? tanh_fast(pre) : sig_fast(pre);
                gbuf[g] = gv;
                // publish xw1[tj-1] = Wx1 . h0[tj-1] + b1 (h_s holds h0[tj-1])
                if (tj > 0) xwo[(size_t)(tj - 1) * G4_] = sq.x + sq.y + b1g;
                __syncthreads();

                if (g < F_) {
                    float iv = gbuf[g];
                    float fv = gbuf[g + 64];
                    float gg = gbuf[g + 128];
                    float ov = gbuf[g + 192];
                    c_reg = fv * c_reg + iv * gg;
                    h_s[g] = ov * tanh_fast(c_reg);
                }
                __syncthreads();
            }
            if ((t & 4) && g == 0) {
                __threadfence();
                *(volatile int*)&prog[b] = t + 3;
            }
        }
        // epilogue: publish xw1[S-1] using final h0[S-1]
        {
            ull q0 = 0, q1 = 0, q2 = 0, q3 = 0;
#pragma unroll
            for (int k4 = 0; k4 < 16; k4 += 2) {
                ulonglong2 hA = h4[k4];
                ulonglong2 hB = h4[k4 + 1];
                q0 = fma2(hA.x, wB[2 * k4 + 0], q0);
                q1 = fma2(hA.y, wB[2 * k4 + 1], q1);
                q2 = fma2(hB.x, wB[2 * k4 + 2], q2);
                q3 = fma2(hB.y, wB[2 * k4 + 3], q3);
            }
            q0 = add2(add2(q0, q1), add2(q2, q3));
            float2 sq = upk2(q0);
            xwo[(size_t)(S_ - 1) * G4_] = sq.x + sq.y + b1g;
        }
        __syncthreads();
        if (g == 0) {
            __threadfence();
            *(volatile int*)&prog[b] = S_;
        }
    } else {
        // ---------------- consumer: layer1 recurrence ----------------
        ull w2[32];
#pragma unroll
        for (int k2 = 0; k2 < 32; k2++) {
            w2[k2] = pk2(Wh1[(size_t)(2 * k2) * G4_ + g],
                         Wh1[(size_t)(2 * k2 + 1) * G4_ + g]);
        }

        if (g < F_) h_s[g] = 0.0f;
        float c_reg = 0.0f;

        const float* xwb = xw1 + (size_t)b * S_ * G4_ + g;
        const volatile int* pf = &prog[b];
        int seen = 0;

        {
            int need = (8 < S_) ? 8 : S_;
            while (seen < need) { seen = *pf; if (seen < need) __nanosleep(64); }
            __threadfence();
        }
        float xwbuf[4];
#pragma unroll
        for (int j = 0; j < 4; j++) xwbuf[j] = __ldcg(xwb + (size_t)j * G4_);
        __syncthreads();

        for (int t = 0; t < S_; t += 4) {
            int need = (t + 8 < S_) ? (t + 8) : S_;
            if (seen < need) {
                while (seen < need) { seen = *pf; if (seen < need) __nanosleep(64); }
                __threadfence();
            }
#pragma unroll
            for (int j = 0; j < 4; j++) {
                float xv = xwbuf[j];
                int tn = t + 4 + j;
                if (tn < S_) xwbuf[j] = __ldcg(xwb + (size_t)tn * G4_);

                ull a0 = 0, a1 = 0, a2 = 0, a3 = 0;
#pragma unroll
                for (int k4 = 0; k4 < 16; k4 += 2) {
                    ulonglong2 hA = h4[k4];
                    ulonglong2 hB = h4[k4 + 1];
                    a0 = fma2(hA.x, w2[2 * k4 + 0], a0);
                    a1 = fma2(hA.y, w2[2 * k4 + 1], a1);
                    a2 = fma2(hB.x, w2[2 * k4 + 2], a2);
                    a3 = fma2(hB.y, w2[2 * k4 + 3], a3);
                }
                a0 = add2(add2(a0, a1), add2(a2, a3));
                float2 sv = upk2(a0);
                float pre = sv.x + sv.y + xv;

                float gv = (gtype == 2) ? tanh_fast(pre) : sig_fast(pre);
                gbuf[g] = gv;
                __syncthreads();

                if (g < F_) {
                    float iv = gbuf[g];
                    float fv = gbuf[g + 64];
                    float gg = gbuf[g + 128];
                    float ov = gbuf[g + 192];
                    c_reg = fv * c_reg + iv * gg;
                    h_s[g] = ov * tanh_fast(c_reg);
                }
                __syncthreads();
            }
        }
        if (g < F_) c_final[b * F_ + g] = c_reg;
    }
}

// ---------------------------------------------------------------------------
// Tiny dense head
// ---------------------------------------------------------------------------
__global__ void dense_head(const float* __restrict__ cf,
                           const float* __restrict__ wd,
                           const float* __restrict__ bd,
                           float* __restrict__ out) {
    int t = threadIdx.x;
    if (t >= B_ * 10) return;
    int b = t / 10, n = t % 10;
    float s = bd[n];
#pragma unroll
    for (int k = 0; k < F_; k++) s += cf[b * F_ + k] * wd[k * 10 + n];
    out[b * 10 + n] = s;
}

// ---------------------------------------------------------------------------
extern "C" void kernel_launch(void* const* d_in, const int* in_sizes, int n_in,
                              void* d_out, int out_size) {
    const float* x       = (const float*)d_in[0];
    const float* conv_w0 = (const float*)d_in[1];
    const float* conv_b0 = (const float*)d_in[2];
    const float* conv_w1 = (const float*)d_in[3];
    const float* conv_b1 = (const float*)d_in[4];
    const float* conv_w2 = (const float*)d_in[5];
    const float* conv_b2 = (const float*)d_in[6];
    const float* Wx0     = (const float*)d_in[7];
    const float* Wh0     = (const float*)d_in[8];
    const float* b0      = (const float*)d_in[9];
    const float* Wx1     = (const float*)d_in[10];
    const float* Wh1     = (const float*)d_in[11];
    const float* b1      = (const float*)d_in[12];
    const float* dense_w = (const float*)d_in[13];
    const float* dense_b = (const float*)d_in[14];
    float* out = (float*)d_out;

    void *pA, *pB, *pXW0, *pXW1, *pPR, *pCF;
    cudaGetSymbolAddress(&pA, g_bufA);
    cudaGetSymbolAddress(&pB, g_bufB);
    cudaGetSymbolAddress(&pXW0, g_xw0);
    cudaGetSymbolAddress(&pXW1, g_xw1);
    cudaGetSymbolAddress(&pPR, g_prog);
    cudaGetSymbolAddress(&pCF, g_cfinal);
    float* bufA = (float*)pA;
    float* bufB = (float*)pB;
    float* xw0  = (float*)pXW0;
    float* xw1  = (float*)pXW1;
    int*   prog = (int*)pPR;
    float* cfin = (float*)pCF;

    dim3 convGrid(S_ / 64, 1, B_);
    dim3 gemmGrid(S_ / 64, G4_ / 64, B_);

    // CNN stack
    conv_gemm<3, true><<<convGrid, 256>>>(x, conv_w0, conv_b0, bufA, 128, 64);
    conv_gemm<3, true><<<convGrid, 256>>>(bufA, conv_w1, conv_b1, bufB, 64, 64);
    conv_gemm<3, true><<<convGrid, 256>>>(bufB, conv_w2, conv_b2, bufA, 64, 64);

    // LSTM layer0 input projection (big parallel GEMM)
    conv_gemm<1, false><<<gemmGrid, 256>>>(bufA, Wx0, b0, xw0, 64, 256);

    // Pipelined 2-layer recurrence (layer1 xw computed by producers on the fly)
    lstm_pipe<<<2 * B_, 256>>>(xw0, Wh0, Wx1, b1, Wh1, xw1, prog, cfin);

    // Dense head
    dense_head<<<1, B_ * 10>>>(cfin, dense_w, dense_b, out);
}